// round 12
// baseline (speedup 1.0000x reference)
#include <cuda_runtime.h>
#include <cstdint>

#define N_PTS   131072
#define C_DIM   64
#define K_CB    512
#define NQ      4
#define HW_SZ   16384
#define P_BLK   16
#define NTHR    256
#define NBLK    (N_PTS / P_BLK)
#define WLCAP   1024
#define IDX_OFF 8388608
#define LOSS_OFF 8912896

typedef unsigned long long ull;

// Scratch (allocation-free rule: __device__ globals)
__device__ float    g_G[K_CB * K_CB];    // NEGATED Gram -cb@cb.T (fast path)
__device__ float    g_h[K_CB];           // NEGATED half-norms -0.5||c||^2
__device__ float    g_csq[K_CB];         // ||c||^2, XLA-CPU vectorized-reduce order
__device__ float    g_cbT[C_DIM * K_CB]; // transposed codebook [c][k]
__device__ double   g_loss[NQ];
__device__ unsigned g_done = 0;

// Packed fp32x2 ops (sm_10x). Per-lane rn rounding == scalar fmaf/fadd.
__device__ __forceinline__ ull fma2(ull a, ull b, ull c) {
    ull d;
    asm("fma.rn.f32x2 %0, %1, %2, %3;" : "=l"(d) : "l"(a), "l"(b), "l"(c));
    return d;
}
__device__ __forceinline__ ull add2(ull a, ull b) {
    ull d;
    asm("add.rn.f32x2 %0, %1, %2;" : "=l"(d) : "l"(a), "l"(b));
    return d;
}
__device__ __forceinline__ ull pack2(float lo, float hi) {
    ull d;
    asm("mov.b64 %0, {%1, %2};" : "=l"(d) : "f"(lo), "f"(hi));
    return d;
}
__device__ __forceinline__ void unpack2(float& lo, float& hi, ull v) {
    asm("mov.b64 {%0, %1}, %2;" : "=f"(lo), "=f"(hi) : "l"(v));
}

// ---------------------------------------------------------------------------
// Precompute (negated) G, (negated) h, csq, cbT; zero loss accumulators.
// ---------------------------------------------------------------------------
__global__ void prep_kernel(const float* __restrict__ cb) {
    __shared__ float ci[C_DIM];
    const int i = blockIdx.x;
    const int t = threadIdx.x;
    if (t < C_DIM) ci[t] = cb[i * C_DIM + t];
    __syncthreads();
    {
        const float4* row = (const float4*)(cb + t * C_DIM);
        float s = 0.f;
#pragma unroll
        for (int c4 = 0; c4 < 16; c4++) {
            float4 v = row[c4];
            s = fmaf(ci[4 * c4 + 0], v.x, s);
            s = fmaf(ci[4 * c4 + 1], v.y, s);
            s = fmaf(ci[4 * c4 + 2], v.z, s);
            s = fmaf(ci[4 * c4 + 3], v.w, s);
        }
        g_G[i * K_CB + t] = -s;                 // negated for packed-add subtract
        if (t == i) g_h[i] = -0.5f * s;         // negated half-norm
    }
    if (t < C_DIM) g_cbT[t * K_CB + i] = ci[t]; // transposed copy
    if (t == 0) {
        // csq exactly as XLA:CPU vectorized reduce (NEON width 4):
        // 4 strided lane accumulators, strict per-op rounding (mul+add,
        // no FMA), shuffle-halving horizontal sum: (L0+L2)+(L1+L3).
        float l0 = 0.f, l1 = 0.f, l2 = 0.f, l3 = 0.f;
        for (int j = 0; j < 16; j++) {
            float v0 = ci[4 * j + 0], v1 = ci[4 * j + 1];
            float v2 = ci[4 * j + 2], v3 = ci[4 * j + 3];
            l0 = __fadd_rn(l0, __fmul_rn(v0, v0));
            l1 = __fadd_rn(l1, __fmul_rn(v1, v1));
            l2 = __fadd_rn(l2, __fmul_rn(v2, v2));
            l3 = __fadd_rn(l3, __fmul_rn(v3, v3));
        }
        g_csq[i] = __fadd_rn(__fadd_rn(l0, l2), __fadd_rn(l1, l3));
    }
    if (i == 0 && t < NQ) g_loss[t] = 0.0;
}

// Orderable-float packing: larger float -> larger uint (monotone).
__device__ __forceinline__ unsigned ford(float f) {
    unsigned u = __float_as_uint(f);
    return (u & 0x80000000u) ? ~u : (u | 0x80000000u);
}

// ---------------------------------------------------------------------------
// Main fused RVQ kernel. Block = 16 points x 512 codewords, 256 threads,
// 4 blocks/SM. Thread tile: 4 points (pg=tid&3, pairs packed) x 8 k's
// (kg=tid>>2) -> acc2[2][8] = 32 regs. Candidate window uses per-warp
// per-point maxima (shfl only, no atomics/barrier); redmin double-buffered
// so each stage needs only 3 syncthreads.
// ---------------------------------------------------------------------------
__global__ __launch_bounds__(NTHR, 4)
void rvq_kernel(const float* __restrict__ x, const float* __restrict__ cb,
                float* __restrict__ out) {
    __shared__ __align__(16) float rs[C_DIM][P_BLK]; // exact residual (4KB)
    __shared__ ull    redmin[2][P_BLK];              // packed (dist,k), dbl-buf
    __shared__ int    idxs[NQ][P_BLK];
    __shared__ double sloss[NQ];
    __shared__ int    wl[WLCAP];                     // candidates (p<<9|k)
    __shared__ int    wl_n;

    const int tid   = threadIdx.x;
    const int lane  = tid & 31;
    const int pg    = tid & 3;                  // 0..3, 4 points each
    const int kg    = tid >> 2;                 // 0..63
    const int kbase = kg * 8;
    const int n0    = blockIdx.x * P_BLK;
    const int b     = n0 / HW_SZ;               // 16 | HW, block never crosses b
    const int hw0   = n0 % HW_SZ;
    const float* xbase = x + (size_t)b * C_DIM * HW_SZ + hw0;

    if (tid < P_BLK) { redmin[0][tid] = ~0ull; redmin[1][tid] = ~0ull; }
    if (tid < NQ)    sloss[tid] = 0.0;
    if (tid == 0)    wl_n = 0;

    const int p_e  = tid & 15;       // elementwise-phase point
    const int cg_e = tid >> 4;       // elementwise-phase channel group (0..15)

    // ---- load x tile (coalesced over p); rs starts as x (exact residual) ----
#pragma unroll
    for (int ii = 0; ii < 4; ii++) {
        const int c = cg_e * 4 + ii;
        rs[c][p_e] = xbase[(size_t)c * HW_SZ + p_e];
    }

    // ---- acc init: packed (-0.5||c_k||^2), same value both point-halves ----
    ull acc2[2][8];
    {
        float hv[8];
        ((float4*)hv)[0] = *((const float4*)(g_h + kbase));
        ((float4*)hv)[1] = *((const float4*)(g_h + kbase + 4));
#pragma unroll
        for (int j = 0; j < 8; j++) {
            ull hj = pack2(hv[j], hv[j]);
            acc2[0][j] = hj; acc2[1][j] = hj;
        }
    }
    __syncthreads();

    // ---- barrier-free matmul: acc += x[pair] * cbT[c][k] ----
    // Per (p,k) cell: one fma.rn per ascending c — byte-identical chain to
    // the validated versions.
    {
        const float4* cvp = (const float4*)(g_cbT + kbase);
#pragma unroll 4
        for (int c = 0; c < C_DIM; c++) {
            ulonglong2 xx = *((const ulonglong2*)&rs[c][pg * 4]); // (p0,p1),(p2,p3)
            float4 cva = __ldg(cvp + (size_t)c * (K_CB / 4));
            float4 cvb = __ldg(cvp + (size_t)c * (K_CB / 4) + 1);
            float cvf[8] = {cva.x, cva.y, cva.z, cva.w,
                            cvb.x, cvb.y, cvb.z, cvb.w};
#pragma unroll
            for (int j = 0; j < 8; j++) {
                ull cj = pack2(cvf[j], cvf[j]);
                acc2[0][j] = fma2(xx.x, cj, acc2[0][j]);
                acc2[1][j] = fma2(xx.y, cj, acc2[1][j]);
            }
        }
    }

    float qsum[4];                   // quantized accumulator (4 channels of p_e)
#pragma unroll
    for (int ii = 0; ii < 4; ii++) qsum[ii] = 0.f;

    // ---- 4 quantizer stages, 3 syncs each ----
#pragma unroll
    for (int q = 0; q < NQ; q++) {
        const int buf = q & 1;

        // P1: per-warp per-point max via shfl (lanes sharing pg differ in
        //     lane bits 2..4); push cells within window of the warp-local
        //     max. Superset of the global-window candidate set -> exact
        //     path still returns the reference argmin.
#pragma unroll
        for (int i = 0; i < 2; i++) {
            float lo[8], hi[8];
#pragma unroll
            for (int j = 0; j < 8; j++) unpack2(lo[j], hi[j], acc2[i][j]);
            float ml = lo[0], mh = hi[0];
#pragma unroll
            for (int j = 1; j < 8; j++) {
                ml = fmaxf(ml, lo[j]); mh = fmaxf(mh, hi[j]);
            }
            ml = fmaxf(ml, __shfl_xor_sync(0xffffffffu, ml, 4));
            ml = fmaxf(ml, __shfl_xor_sync(0xffffffffu, ml, 8));
            ml = fmaxf(ml, __shfl_xor_sync(0xffffffffu, ml, 16));
            mh = fmaxf(mh, __shfl_xor_sync(0xffffffffu, mh, 4));
            mh = fmaxf(mh, __shfl_xor_sync(0xffffffffu, mh, 8));
            mh = fmaxf(mh, __shfl_xor_sync(0xffffffffu, mh, 16));
            const float tl = ml - 0.01f, th = mh - 0.01f;
            const int pA = pg * 4 + 2 * i, pB = pA + 1;
#pragma unroll
            for (int j = 0; j < 8; j++) {
                if (lo[j] >= tl) {
                    int pos = atomicAdd(&wl_n, 1);
                    if (pos < WLCAP) wl[pos] = (pA << 9) | (kbase + j);
                }
                if (hi[j] >= th) {
                    int pos = atomicAdd(&wl_n, 1);
                    if (pos < WLCAP) wl[pos] = (pB << 9) | (kbase + j);
                }
            }
        }
        __syncthreads();

        // P2: exact (reference-order) dist per candidate, one thread each
        {
            const int wn = (wl_n < WLCAP) ? wl_n : WLCAP;
            for (int t = tid; t < wn; t += NTHR) {
                const int e = wl[t];
                const int p = e >> 9;
                const int k = e & 511;
                const float4* c4 = (const float4*)(cb + k * C_DIM);
                float dot = 0.f;
#pragma unroll 4
                for (int g = 0; g < 16; g++) {           // ascending-c seq FMA
                    float4 v = c4[g];                     // (Eigen gebp order)
                    dot = fmaf(rs[4 * g + 0][p], v.x, dot);
                    dot = fmaf(rs[4 * g + 1][p], v.y, dot);
                    dot = fmaf(rs[4 * g + 2][p], v.z, dot);
                    dot = fmaf(rs[4 * g + 3][p], v.w, dot);
                }
                float dist = __fsub_rn(g_csq[k], __fmul_rn(2.0f, dot));
                ull pk = ((ull)ford(dist) << 32) | (unsigned)k;
                atomicMin(&redmin[buf][p], pk);          // min dist, then min k
            }
        }
        __syncthreads();

        // P3: exact elementwise update + cascade + bookkeeping (one sync)
        {
            const int k = (int)(unsigned)(redmin[buf][p_e] & 0xffffffffull);
            const float* crow = cb + k * C_DIM + cg_e * 4;
            double ls = 0.0;
#pragma unroll
            for (int ii = 0; ii < 4; ii++) {
                const int c = cg_e * 4 + ii;
                const float cv = crow[ii];
                const float r  = rs[c][p_e];
                const float d  = __fsub_rn(cv, r);          // quant - residual
                const float qst = __fadd_rn(r, d);          // straight-through
                qsum[ii] = __fadd_rn(qsum[ii], qst);        // quant_out += qst
                rs[c][p_e] = __fsub_rn(r, cv);              // residual -= quant
                ls += (double)__fmul_rn(d, d);
            }
#pragma unroll
            for (int o = 16; o; o >>= 1)
                ls += __shfl_xor_sync(0xffffffffu, ls, o);
            if (lane == 0) atomicAdd(&sloss[q], ls);
        }
        if (q < NQ - 1) {
            // fast-score cascade: acc += (-G[idx]) slices, point-pair packed
#pragma unroll
            for (int i = 0; i < 2; i++) {
                const int pA = pg * 4 + 2 * i;
                const int rA = (int)(unsigned)(redmin[buf][pA] & 0xffffffffull);
                const int rB = (int)(unsigned)(redmin[buf][pA + 1] & 0xffffffffull);
                const float4* ga = (const float4*)(g_G + (size_t)rA * K_CB + kbase);
                const float4* gb = (const float4*)(g_G + (size_t)rB * K_CB + kbase);
                float4 ga0 = ga[0], ga1 = ga[1];
                float4 gb0 = gb[0], gb1 = gb[1];
                acc2[i][0] = add2(acc2[i][0], pack2(ga0.x, gb0.x));
                acc2[i][1] = add2(acc2[i][1], pack2(ga0.y, gb0.y));
                acc2[i][2] = add2(acc2[i][2], pack2(ga0.z, gb0.z));
                acc2[i][3] = add2(acc2[i][3], pack2(ga0.w, gb0.w));
                acc2[i][4] = add2(acc2[i][4], pack2(ga1.x, gb1.x));
                acc2[i][5] = add2(acc2[i][5], pack2(ga1.y, gb1.y));
                acc2[i][6] = add2(acc2[i][6], pack2(ga1.z, gb1.z));
                acc2[i][7] = add2(acc2[i][7], pack2(ga1.w, gb1.w));
            }
        }
        if (tid < P_BLK) {
            idxs[q][tid] = (int)(unsigned)(redmin[buf][tid] & 0xffffffffull);
            redmin[buf ^ 1][tid] = ~0ull;       // prep other buffer (idle now)
        }
        if (tid == 0) wl_n = 0;
        __syncthreads();
    }

    // ---- outputs ----
    // indices as float, coalesced: 64 threads cover 16 points x 4 stages
    if (tid < P_BLK * NQ) {
        const int q = tid & 3, p = tid >> 2;
        out[IDX_OFF + (size_t)(n0 + p) * NQ + q] = (float)idxs[q][p];
    }
    // quantized in [B,C,H,W] layout (coalesced over p)
    {
        float* obase = out + (size_t)b * C_DIM * HW_SZ + hw0 + p_e;
#pragma unroll
        for (int ii = 0; ii < 4; ii++) {
            const int c = cg_e * 4 + ii;
            obase[(size_t)c * HW_SZ] = qsum[ii];
        }
    }
    // commit losses: 4 global atomics per block, last block writes output
    if (tid < NQ) atomicAdd(&g_loss[tid], sloss[tid]);
    __syncthreads();
    if (tid == 0) {
        __threadfence();
        unsigned t = atomicAdd(&g_done, 1u);
        if (t == (unsigned)(gridDim.x - 1)) {
            __threadfence();
            g_done = 0;                        // reset for next launch/replay
#pragma unroll
            for (int qq = 0; qq < NQ; qq++)
                out[LOSS_OFF + qq] =
                    (float)(g_loss[qq] * (1.0 / (131072.0 * 64.0)));
        }
    }
}

extern "C" void kernel_launch(void* const* d_in, const int* in_sizes, int n_in,
                              void* d_out, int out_size) {
    (void)in_sizes; (void)n_in; (void)out_size;
    const float* x  = (const float*)d_in[0];
    const float* cb = (const float*)d_in[1];
    float* out = (float*)d_out;

    prep_kernel<<<K_CB, 512>>>(cb);
    rvq_kernel<<<NBLK, NTHR>>>(x, cb, out);
}

// round 13
// speedup vs baseline: 1.1093x; 1.1093x over previous
#include <cuda_runtime.h>
#include <cstdint>

#define N_PTS   131072
#define C_DIM   64
#define K_CB    512
#define NQ      4
#define HW_SZ   16384
#define P_BLK   16
#define NTHR    256
#define NBLK    (N_PTS / P_BLK)
#define WLCAP   1024
#define IDX_OFF 8388608
#define LOSS_OFF 8912896

typedef unsigned long long ull;

// Scratch (allocation-free rule: __device__ globals)
__device__ float    g_G[K_CB * K_CB];    // NEGATED Gram -cb@cb.T (fast path)
__device__ float    g_h[K_CB];           // NEGATED half-norms -0.5||c||^2
__device__ float    g_csq[K_CB];         // ||c||^2, XLA-CPU vectorized-reduce order
__device__ float    g_cbT[C_DIM * K_CB]; // transposed codebook [c][k]
__device__ double   g_loss[NQ];
__device__ unsigned g_done = 0;

// Packed fp32x2 ops (sm_10x). Per-lane rn rounding == scalar fmaf/fadd.
__device__ __forceinline__ ull fma2(ull a, ull b, ull c) {
    ull d;
    asm("fma.rn.f32x2 %0, %1, %2, %3;" : "=l"(d) : "l"(a), "l"(b), "l"(c));
    return d;
}
__device__ __forceinline__ ull add2(ull a, ull b) {
    ull d;
    asm("add.rn.f32x2 %0, %1, %2;" : "=l"(d) : "l"(a), "l"(b));
    return d;
}
__device__ __forceinline__ ull pack2(float lo, float hi) {
    ull d;
    asm("mov.b64 %0, {%1, %2};" : "=l"(d) : "f"(lo), "f"(hi));
    return d;
}
__device__ __forceinline__ void unpack2(float& lo, float& hi, ull v) {
    asm("mov.b64 {%0, %1}, %2;" : "=f"(lo), "=f"(hi) : "l"(v));
}

// ---------------------------------------------------------------------------
// Precompute (negated) G, (negated) h, csq, cbT; zero loss accumulators.
// ---------------------------------------------------------------------------
__global__ void prep_kernel(const float* __restrict__ cb) {
    __shared__ float ci[C_DIM];
    const int i = blockIdx.x;
    const int t = threadIdx.x;
    if (t < C_DIM) ci[t] = cb[i * C_DIM + t];
    __syncthreads();
    {
        const float4* row = (const float4*)(cb + t * C_DIM);
        float s = 0.f;
#pragma unroll
        for (int c4 = 0; c4 < 16; c4++) {
            float4 v = row[c4];
            s = fmaf(ci[4 * c4 + 0], v.x, s);
            s = fmaf(ci[4 * c4 + 1], v.y, s);
            s = fmaf(ci[4 * c4 + 2], v.z, s);
            s = fmaf(ci[4 * c4 + 3], v.w, s);
        }
        g_G[i * K_CB + t] = -s;                 // negated for packed-add subtract
        if (t == i) g_h[i] = -0.5f * s;         // negated half-norm
    }
    if (t < C_DIM) g_cbT[t * K_CB + i] = ci[t]; // transposed copy
    if (t == 0) {
        // csq exactly as XLA:CPU vectorized reduce (NEON width 4):
        // 4 strided lane accumulators, strict per-op rounding (mul+add,
        // no FMA), shuffle-halving horizontal sum: (L0+L2)+(L1+L3).
        float l0 = 0.f, l1 = 0.f, l2 = 0.f, l3 = 0.f;
        for (int j = 0; j < 16; j++) {
            float v0 = ci[4 * j + 0], v1 = ci[4 * j + 1];
            float v2 = ci[4 * j + 2], v3 = ci[4 * j + 3];
            l0 = __fadd_rn(l0, __fmul_rn(v0, v0));
            l1 = __fadd_rn(l1, __fmul_rn(v1, v1));
            l2 = __fadd_rn(l2, __fmul_rn(v2, v2));
            l3 = __fadd_rn(l3, __fmul_rn(v3, v3));
        }
        g_csq[i] = __fadd_rn(__fadd_rn(l0, l2), __fadd_rn(l1, l3));
    }
    if (i == 0 && t < NQ) g_loss[t] = 0.0;
}

// Orderable-float packing: larger float -> larger uint (monotone).
__device__ __forceinline__ unsigned ford(float f) {
    unsigned u = __float_as_uint(f);
    return (u & 0x80000000u) ? ~u : (u | 0x80000000u);
}

// ---------------------------------------------------------------------------
// Main fused RVQ kernel. Block = 16 points x 512 codewords, 256 threads,
// 4 blocks/SM. Thread tile (R11-validated): 8 points (pg=tid&1, pairs
// packed) x 4 k's (kg=tid>>1) -> acc2[4][4] = 32 regs; 1 LDG.128 + 2
// LDS.128 per channel. Stage machinery (R12-validated): per-warp window
// via shfl only, redmin double-buffered, 3 syncthreads per stage.
// ---------------------------------------------------------------------------
__global__ __launch_bounds__(NTHR, 4)
void rvq_kernel(const float* __restrict__ x, const float* __restrict__ cb,
                float* __restrict__ out) {
    __shared__ __align__(16) float rs[C_DIM][P_BLK]; // exact residual (4KB)
    __shared__ ull    redmin[2][P_BLK];              // packed (dist,k), dbl-buf
    __shared__ int    idxs[NQ][P_BLK];
    __shared__ double sloss[NQ];
    __shared__ int    wl[WLCAP];                     // candidates (p<<9|k)
    __shared__ int    wl_n;

    const int tid   = threadIdx.x;
    const int lane  = tid & 31;
    const int pg    = tid & 1;                  // 0..1, 8 points each
    const int kg    = tid >> 1;                 // 0..127
    const int kbase = kg * 4;
    const int n0    = blockIdx.x * P_BLK;
    const int b     = n0 / HW_SZ;               // 16 | HW, block never crosses b
    const int hw0   = n0 % HW_SZ;
    const float* xbase = x + (size_t)b * C_DIM * HW_SZ + hw0;

    if (tid < P_BLK) { redmin[0][tid] = ~0ull; redmin[1][tid] = ~0ull; }
    if (tid < NQ)    sloss[tid] = 0.0;
    if (tid == 0)    wl_n = 0;

    const int p_e  = tid & 15;       // elementwise-phase point
    const int cg_e = tid >> 4;       // elementwise-phase channel group (0..15)

    // ---- load x tile (coalesced over p); rs starts as x (exact residual) ----
#pragma unroll
    for (int ii = 0; ii < 4; ii++) {
        const int c = cg_e * 4 + ii;
        rs[c][p_e] = xbase[(size_t)c * HW_SZ + p_e];
    }

    // ---- acc init: packed (-0.5||c_k||^2), same value both point-halves ----
    ull acc2[4][4];
    {
        float4 hv = *((const float4*)(g_h + kbase));
        ull h0 = pack2(hv.x, hv.x), h1 = pack2(hv.y, hv.y);
        ull h2 = pack2(hv.z, hv.z), h3 = pack2(hv.w, hv.w);
#pragma unroll
        for (int i = 0; i < 4; i++) {
            acc2[i][0] = h0; acc2[i][1] = h1;
            acc2[i][2] = h2; acc2[i][3] = h3;
        }
    }
    __syncthreads();

    // ---- barrier-free matmul (R11 tile): acc += x[pair] * cbT[c][k] ----
    // Per (p,k) cell: one fma.rn per ascending c — byte-identical chain to
    // the validated versions.
    {
        const float4* cvp = (const float4*)(g_cbT + kbase);
#pragma unroll 4
        for (int c = 0; c < C_DIM; c++) {
            ulonglong2 xa = *((const ulonglong2*)&rs[c][pg * 8]);     // (p0,p1),(p2,p3)
            ulonglong2 xb = *((const ulonglong2*)&rs[c][pg * 8 + 4]); // (p4,p5),(p6,p7)
            float4 cv = __ldg(cvp + (size_t)c * (K_CB / 4));
            ull c0 = pack2(cv.x, cv.x), c1 = pack2(cv.y, cv.y);
            ull c2 = pack2(cv.z, cv.z), c3 = pack2(cv.w, cv.w);
            acc2[0][0] = fma2(xa.x, c0, acc2[0][0]);
            acc2[0][1] = fma2(xa.x, c1, acc2[0][1]);
            acc2[0][2] = fma2(xa.x, c2, acc2[0][2]);
            acc2[0][3] = fma2(xa.x, c3, acc2[0][3]);
            acc2[1][0] = fma2(xa.y, c0, acc2[1][0]);
            acc2[1][1] = fma2(xa.y, c1, acc2[1][1]);
            acc2[1][2] = fma2(xa.y, c2, acc2[1][2]);
            acc2[1][3] = fma2(xa.y, c3, acc2[1][3]);
            acc2[2][0] = fma2(xb.x, c0, acc2[2][0]);
            acc2[2][1] = fma2(xb.x, c1, acc2[2][1]);
            acc2[2][2] = fma2(xb.x, c2, acc2[2][2]);
            acc2[2][3] = fma2(xb.x, c3, acc2[2][3]);
            acc2[3][0] = fma2(xb.y, c0, acc2[3][0]);
            acc2[3][1] = fma2(xb.y, c1, acc2[3][1]);
            acc2[3][2] = fma2(xb.y, c2, acc2[3][2]);
            acc2[3][3] = fma2(xb.y, c3, acc2[3][3]);
        }
    }

    float qsum[4];                   // quantized accumulator (4 channels of p_e)
#pragma unroll
    for (int ii = 0; ii < 4; ii++) qsum[ii] = 0.f;

    // ---- 4 quantizer stages, 3 syncs each ----
#pragma unroll
    for (int q = 0; q < NQ; q++) {
        const int buf = q & 1;

        // P1: per-warp per-point max via shfl (lanes sharing pg differ in
        //     lane bits 1..4); push cells within window of the warp-local
        //     max. Superset of the global-window candidate set -> exact
        //     path still returns the reference argmin.
#pragma unroll
        for (int i = 0; i < 4; i++) {
            float lo[4], hi[4];
#pragma unroll
            for (int j = 0; j < 4; j++) unpack2(lo[j], hi[j], acc2[i][j]);
            float ml = fmaxf(fmaxf(lo[0], lo[1]), fmaxf(lo[2], lo[3]));
            float mh = fmaxf(fmaxf(hi[0], hi[1]), fmaxf(hi[2], hi[3]));
            ml = fmaxf(ml, __shfl_xor_sync(0xffffffffu, ml, 2));
            ml = fmaxf(ml, __shfl_xor_sync(0xffffffffu, ml, 4));
            ml = fmaxf(ml, __shfl_xor_sync(0xffffffffu, ml, 8));
            ml = fmaxf(ml, __shfl_xor_sync(0xffffffffu, ml, 16));
            mh = fmaxf(mh, __shfl_xor_sync(0xffffffffu, mh, 2));
            mh = fmaxf(mh, __shfl_xor_sync(0xffffffffu, mh, 4));
            mh = fmaxf(mh, __shfl_xor_sync(0xffffffffu, mh, 8));
            mh = fmaxf(mh, __shfl_xor_sync(0xffffffffu, mh, 16));
            const float tl = ml - 0.01f, th = mh - 0.01f;
            const int pA = pg * 8 + 2 * i, pB = pA + 1;
#pragma unroll
            for (int j = 0; j < 4; j++) {
                if (lo[j] >= tl) {
                    int pos = atomicAdd(&wl_n, 1);
                    if (pos < WLCAP) wl[pos] = (pA << 9) | (kbase + j);
                }
                if (hi[j] >= th) {
                    int pos = atomicAdd(&wl_n, 1);
                    if (pos < WLCAP) wl[pos] = (pB << 9) | (kbase + j);
                }
            }
        }
        __syncthreads();

        // P2: exact (reference-order) dist per candidate, one thread each
        {
            const int wn = (wl_n < WLCAP) ? wl_n : WLCAP;
            for (int t = tid; t < wn; t += NTHR) {
                const int e = wl[t];
                const int p = e >> 9;
                const int k = e & 511;
                const float4* c4 = (const float4*)(cb + k * C_DIM);
                float dot = 0.f;
#pragma unroll 4
                for (int g = 0; g < 16; g++) {           // ascending-c seq FMA
                    float4 v = c4[g];                     // (Eigen gebp order)
                    dot = fmaf(rs[4 * g + 0][p], v.x, dot);
                    dot = fmaf(rs[4 * g + 1][p], v.y, dot);
                    dot = fmaf(rs[4 * g + 2][p], v.z, dot);
                    dot = fmaf(rs[4 * g + 3][p], v.w, dot);
                }
                float dist = __fsub_rn(g_csq[k], __fmul_rn(2.0f, dot));
                ull pk = ((ull)ford(dist) << 32) | (unsigned)k;
                atomicMin(&redmin[buf][p], pk);          // min dist, then min k
            }
        }
        __syncthreads();

        // P3: exact elementwise update + cascade + bookkeeping (one sync)
        {
            const int k = (int)(unsigned)(redmin[buf][p_e] & 0xffffffffull);
            const float* crow = cb + k * C_DIM + cg_e * 4;
            double ls = 0.0;
#pragma unroll
            for (int ii = 0; ii < 4; ii++) {
                const int c = cg_e * 4 + ii;
                const float cv = crow[ii];
                const float r  = rs[c][p_e];
                const float d  = __fsub_rn(cv, r);          // quant - residual
                const float qst = __fadd_rn(r, d);          // straight-through
                qsum[ii] = __fadd_rn(qsum[ii], qst);        // quant_out += qst
                rs[c][p_e] = __fsub_rn(r, cv);              // residual -= quant
                ls += (double)__fmul_rn(d, d);
            }
#pragma unroll
            for (int o = 16; o; o >>= 1)
                ls += __shfl_xor_sync(0xffffffffu, ls, o);
            if (lane == 0) atomicAdd(&sloss[q], ls);
        }
        if (q < NQ - 1) {
            // fast-score cascade: acc += (-G[idx]) slices, point-pair packed
#pragma unroll
            for (int i = 0; i < 4; i++) {
                const int pA = pg * 8 + 2 * i;
                const int rA = (int)(unsigned)(redmin[buf][pA] & 0xffffffffull);
                const int rB = (int)(unsigned)(redmin[buf][pA + 1] & 0xffffffffull);
                float4 gl = *((const float4*)(g_G + (size_t)rA * K_CB + kbase));
                float4 gh = *((const float4*)(g_G + (size_t)rB * K_CB + kbase));
                acc2[i][0] = add2(acc2[i][0], pack2(gl.x, gh.x));
                acc2[i][1] = add2(acc2[i][1], pack2(gl.y, gh.y));
                acc2[i][2] = add2(acc2[i][2], pack2(gl.z, gh.z));
                acc2[i][3] = add2(acc2[i][3], pack2(gl.w, gh.w));
            }
        }
        if (tid < P_BLK) {
            idxs[q][tid] = (int)(unsigned)(redmin[buf][tid] & 0xffffffffull);
            redmin[buf ^ 1][tid] = ~0ull;       // prep other buffer (idle now)
        }
        if (tid == 0) wl_n = 0;
        __syncthreads();
    }

    // ---- outputs ----
    // indices as float, coalesced: 64 threads cover 16 points x 4 stages
    if (tid < P_BLK * NQ) {
        const int q = tid & 3, p = tid >> 2;
        out[IDX_OFF + (size_t)(n0 + p) * NQ + q] = (float)idxs[q][p];
    }
    // quantized in [B,C,H,W] layout (coalesced over p)
    {
        float* obase = out + (size_t)b * C_DIM * HW_SZ + hw0 + p_e;
#pragma unroll
        for (int ii = 0; ii < 4; ii++) {
            const int c = cg_e * 4 + ii;
            obase[(size_t)c * HW_SZ] = qsum[ii];
        }
    }
    // commit losses: 4 global atomics per block, last block writes output
    if (tid < NQ) atomicAdd(&g_loss[tid], sloss[tid]);
    __syncthreads();
    if (tid == 0) {
        __threadfence();
        unsigned t = atomicAdd(&g_done, 1u);
        if (t == (unsigned)(gridDim.x - 1)) {
            __threadfence();
            g_done = 0;                        // reset for next launch/replay
#pragma unroll
            for (int qq = 0; qq < NQ; qq++)
                out[LOSS_OFF + qq] =
                    (float)(g_loss[qq] * (1.0 / (131072.0 * 64.0)));
        }
    }
}

extern "C" void kernel_launch(void* const* d_in, const int* in_sizes, int n_in,
                              void* d_out, int out_size) {
    (void)in_sizes; (void)n_in; (void)out_size;
    const float* x  = (const float*)d_in[0];
    const float* cb = (const float*)d_in[1];
    float* out = (float*)d_out;

    prep_kernel<<<K_CB, 512>>>(cb);
    rvq_kernel<<<NBLK, NTHR>>>(x, cb, out);
}

// round 14
// speedup vs baseline: 1.4112x; 1.2721x over previous
#include <cuda_runtime.h>
#include <cstdint>

#define N_PTS   131072
#define C_DIM   64
#define K_CB    512
#define NQ      4
#define HW_SZ   16384
#define P_BLK   16
#define NTHR    256
#define NBLK    (N_PTS / P_BLK)
#define WLCAP   512
#define IDX_OFF 8388608
#define LOSS_OFF 8912896

typedef unsigned long long ull;

// Scratch (allocation-free rule: __device__ globals)
__device__ float    g_G[K_CB * K_CB];    // NEGATED Gram -cb@cb.T (fast path)
__device__ float    g_h[K_CB];           // NEGATED half-norms -0.5||c||^2
__device__ float    g_csq[K_CB];         // ||c||^2, XLA-CPU vectorized-reduce order
__device__ float    g_cbT[C_DIM * K_CB]; // transposed codebook [c][k]
__device__ double   g_loss[NQ];
__device__ unsigned g_done = 0;

// Packed fp32x2 ops (sm_10x). Per-lane rn rounding == scalar fmaf/fadd.
__device__ __forceinline__ ull fma2(ull a, ull b, ull c) {
    ull d;
    asm("fma.rn.f32x2 %0, %1, %2, %3;" : "=l"(d) : "l"(a), "l"(b), "l"(c));
    return d;
}
__device__ __forceinline__ ull add2(ull a, ull b) {
    ull d;
    asm("add.rn.f32x2 %0, %1, %2;" : "=l"(d) : "l"(a), "l"(b));
    return d;
}
__device__ __forceinline__ ull pack2(float lo, float hi) {
    ull d;
    asm("mov.b64 %0, {%1, %2};" : "=l"(d) : "f"(lo), "f"(hi));
    return d;
}
__device__ __forceinline__ void unpack2(float& lo, float& hi, ull v) {
    asm("mov.b64 {%0, %1}, %2;" : "=f"(lo), "=f"(hi) : "l"(v));
}

// ---------------------------------------------------------------------------
// Precompute (negated) G, (negated) h, csq, cbT; zero loss accumulators.
// ---------------------------------------------------------------------------
__global__ void prep_kernel(const float* __restrict__ cb) {
    __shared__ float ci[C_DIM];
    const int i = blockIdx.x;
    const int t = threadIdx.x;
    if (t < C_DIM) ci[t] = cb[i * C_DIM + t];
    __syncthreads();
    {
        const float4* row = (const float4*)(cb + t * C_DIM);
        float s = 0.f;
#pragma unroll
        for (int c4 = 0; c4 < 16; c4++) {
            float4 v = row[c4];
            s = fmaf(ci[4 * c4 + 0], v.x, s);
            s = fmaf(ci[4 * c4 + 1], v.y, s);
            s = fmaf(ci[4 * c4 + 2], v.z, s);
            s = fmaf(ci[4 * c4 + 3], v.w, s);
        }
        g_G[i * K_CB + t] = -s;                 // negated for packed-add subtract
        if (t == i) g_h[i] = -0.5f * s;         // negated half-norm
    }
    if (t < C_DIM) g_cbT[t * K_CB + i] = ci[t]; // transposed copy
    if (t == 0) {
        // csq exactly as XLA:CPU vectorized reduce (NEON width 4):
        // 4 strided lane accumulators, strict per-op rounding (mul+add,
        // no FMA), shuffle-halving horizontal sum: (L0+L2)+(L1+L3).
        float l0 = 0.f, l1 = 0.f, l2 = 0.f, l3 = 0.f;
        for (int j = 0; j < 16; j++) {
            float v0 = ci[4 * j + 0], v1 = ci[4 * j + 1];
            float v2 = ci[4 * j + 2], v3 = ci[4 * j + 3];
            l0 = __fadd_rn(l0, __fmul_rn(v0, v0));
            l1 = __fadd_rn(l1, __fmul_rn(v1, v1));
            l2 = __fadd_rn(l2, __fmul_rn(v2, v2));
            l3 = __fadd_rn(l3, __fmul_rn(v3, v3));
        }
        g_csq[i] = __fadd_rn(__fadd_rn(l0, l2), __fadd_rn(l1, l3));
    }
    if (i == 0 && t < NQ) g_loss[t] = 0.0;
}

// Orderable-float packing: larger float -> larger uint (monotone).
__device__ __forceinline__ unsigned ford(float f) {
    unsigned u = __float_as_uint(f);
    return (u & 0x80000000u) ? ~u : (u | 0x80000000u);
}
__device__ __forceinline__ float funord(unsigned s) {
    unsigned u = (s & 0x80000000u) ? (s ^ 0x80000000u) : ~s;
    return __uint_as_float(u);
}

// ---------------------------------------------------------------------------
// Main fused RVQ kernel — R11 structure (global window, 5 syncs/stage),
// with vectorized stage memory access: rs kept in BOTH [c][p] (matmul) and
// padded-transposed [p][c] (exact dots, LDS.128) layouts; phase-D codeword
// row loaded as one LDG.128. Same values, same op order -> identical picks.
// ---------------------------------------------------------------------------
__global__ __launch_bounds__(NTHR, 4)
void rvq_kernel(const float* __restrict__ x, const float* __restrict__ cb,
                float* __restrict__ out) {
    __shared__ __align__(16) float rs[C_DIM][P_BLK];   // residual [c][p] (4KB)
    __shared__ __align__(16) float rs_t[P_BLK][68];    // residual [p][c] (4.25KB)
    __shared__ unsigned red1[P_BLK];            // fast max per point
    __shared__ ull redmin[P_BLK];               // packed (dist,k) argmin
    __shared__ int    idxs[NQ][P_BLK];
    __shared__ double sloss[NQ];
    __shared__ int    wl[WLCAP];                // candidate worklist (p<<9|k)
    __shared__ int    wl_n;

    const int tid   = threadIdx.x;
    const int lane  = tid & 31;
    const int pg    = tid & 1;                  // 0..1, 8 points each
    const int kg    = tid >> 1;                 // 0..127
    const int kbase = kg * 4;
    const int n0    = blockIdx.x * P_BLK;
    const int b     = n0 / HW_SZ;               // 16 | HW, block never crosses b
    const int hw0   = n0 % HW_SZ;
    const float* xbase = x + (size_t)b * C_DIM * HW_SZ + hw0;

    if (tid < P_BLK) { red1[tid] = 0u; redmin[tid] = ~0ull; }
    if (tid < NQ)    sloss[tid] = 0.0;
    if (tid == 0)    wl_n = 0;

    const int p_e  = tid & 15;       // elementwise-phase point
    const int cg_e = tid >> 4;       // elementwise-phase channel group (0..15)

    // ---- load x tile; fill BOTH residual layouts ----
    {
        float v0 = xbase[(size_t)(cg_e * 4 + 0) * HW_SZ + p_e];
        float v1 = xbase[(size_t)(cg_e * 4 + 1) * HW_SZ + p_e];
        float v2 = xbase[(size_t)(cg_e * 4 + 2) * HW_SZ + p_e];
        float v3 = xbase[(size_t)(cg_e * 4 + 3) * HW_SZ + p_e];
        rs[cg_e * 4 + 0][p_e] = v0;
        rs[cg_e * 4 + 1][p_e] = v1;
        rs[cg_e * 4 + 2][p_e] = v2;
        rs[cg_e * 4 + 3][p_e] = v3;
        *((float4*)&rs_t[p_e][cg_e * 4]) = make_float4(v0, v1, v2, v3);
    }

    // ---- acc init: packed (-0.5||c_k||^2), same value both point-halves ----
    ull acc2[4][4];
    {
        float4 hv = *((const float4*)(g_h + kbase));
        ull h0 = pack2(hv.x, hv.x), h1 = pack2(hv.y, hv.y);
        ull h2 = pack2(hv.z, hv.z), h3 = pack2(hv.w, hv.w);
#pragma unroll
        for (int i = 0; i < 4; i++) {
            acc2[i][0] = h0; acc2[i][1] = h1;
            acc2[i][2] = h2; acc2[i][3] = h3;
        }
    }
    __syncthreads();

    // ---- barrier-free matmul (R11 tile): acc += x[pair] * cbT[c][k] ----
    // Per (p,k) cell: one fma.rn per ascending c — byte-identical chain.
    {
        const float4* cvp = (const float4*)(g_cbT + kbase);
#pragma unroll 4
        for (int c = 0; c < C_DIM; c++) {
            ulonglong2 xa = *((const ulonglong2*)&rs[c][pg * 8]);     // (p0,p1),(p2,p3)
            ulonglong2 xb = *((const ulonglong2*)&rs[c][pg * 8 + 4]); // (p4,p5),(p6,p7)
            float4 cv = __ldg(cvp + (size_t)c * (K_CB / 4));
            ull c0 = pack2(cv.x, cv.x), c1 = pack2(cv.y, cv.y);
            ull c2 = pack2(cv.z, cv.z), c3 = pack2(cv.w, cv.w);
            acc2[0][0] = fma2(xa.x, c0, acc2[0][0]);
            acc2[0][1] = fma2(xa.x, c1, acc2[0][1]);
            acc2[0][2] = fma2(xa.x, c2, acc2[0][2]);
            acc2[0][3] = fma2(xa.x, c3, acc2[0][3]);
            acc2[1][0] = fma2(xa.y, c0, acc2[1][0]);
            acc2[1][1] = fma2(xa.y, c1, acc2[1][1]);
            acc2[1][2] = fma2(xa.y, c2, acc2[1][2]);
            acc2[1][3] = fma2(xa.y, c3, acc2[1][3]);
            acc2[2][0] = fma2(xb.x, c0, acc2[2][0]);
            acc2[2][1] = fma2(xb.x, c1, acc2[2][1]);
            acc2[2][2] = fma2(xb.x, c2, acc2[2][2]);
            acc2[2][3] = fma2(xb.x, c3, acc2[2][3]);
            acc2[3][0] = fma2(xb.y, c0, acc2[3][0]);
            acc2[3][1] = fma2(xb.y, c1, acc2[3][1]);
            acc2[3][2] = fma2(xb.y, c2, acc2[3][2]);
            acc2[3][3] = fma2(xb.y, c3, acc2[3][3]);
        }
    }
    __syncthreads();

    float qsum[4];                   // quantized accumulator (4 channels of p_e)
#pragma unroll
    for (int ii = 0; ii < 4; ii++) qsum[ii] = 0.f;

    // ---- 4 quantizer stages (R11 structure) ----
#pragma unroll
    for (int q = 0; q < NQ; q++) {
        // A: fast local max per point; shfl pre-reduce over kg (same-pg lanes
        //    differ in lane bits 1..4), then one smem atomic per (warp,point).
#pragma unroll
        for (int i = 0; i < 4; i++) {
            float l0, h0, l1, h1, l2, h2, l3, h3;
            unpack2(l0, h0, acc2[i][0]);
            unpack2(l1, h1, acc2[i][1]);
            unpack2(l2, h2, acc2[i][2]);
            unpack2(l3, h3, acc2[i][3]);
            float blo = fmaxf(fmaxf(l0, l1), fmaxf(l2, l3));
            float bhi = fmaxf(fmaxf(h0, h1), fmaxf(h2, h3));
            blo = fmaxf(blo, __shfl_xor_sync(0xffffffffu, blo, 2));
            blo = fmaxf(blo, __shfl_xor_sync(0xffffffffu, blo, 4));
            blo = fmaxf(blo, __shfl_xor_sync(0xffffffffu, blo, 8));
            blo = fmaxf(blo, __shfl_xor_sync(0xffffffffu, blo, 16));
            bhi = fmaxf(bhi, __shfl_xor_sync(0xffffffffu, bhi, 2));
            bhi = fmaxf(bhi, __shfl_xor_sync(0xffffffffu, bhi, 4));
            bhi = fmaxf(bhi, __shfl_xor_sync(0xffffffffu, bhi, 8));
            bhi = fmaxf(bhi, __shfl_xor_sync(0xffffffffu, bhi, 16));
            if (lane < 2) {
                atomicMax(&red1[pg * 8 + 2 * i + 0], ford(blo));
                atomicMax(&red1[pg * 8 + 2 * i + 1], ford(bhi));
            }
        }
        __syncthreads();

        // B1: scan tile, push windowed candidates to worklist
#pragma unroll
        for (int i = 0; i < 4; i++) {
            const int pLo = pg * 8 + 2 * i, pHi = pLo + 1;
            const float thrLo = funord(red1[pLo]) - 0.01f;
            const float thrHi = funord(red1[pHi]) - 0.01f;
            float alo[4], ahi[4];
            unpack2(alo[0], ahi[0], acc2[i][0]);
            unpack2(alo[1], ahi[1], acc2[i][1]);
            unpack2(alo[2], ahi[2], acc2[i][2]);
            unpack2(alo[3], ahi[3], acc2[i][3]);
#pragma unroll
            for (int j = 0; j < 4; j++) {
                if (alo[j] >= thrLo) {
                    int pos = atomicAdd(&wl_n, 1);
                    if (pos < WLCAP) wl[pos] = (pLo << 9) | (kbase + j);
                }
                if (ahi[j] >= thrHi) {
                    int pos = atomicAdd(&wl_n, 1);
                    if (pos < WLCAP) wl[pos] = (pHi << 9) | (kbase + j);
                }
            }
        }
        __syncthreads();

        // B2: exact (reference-order) dist per candidate, one thread each.
        //     Residual read from the transposed copy via LDS.128 — same
        //     values, same ascending-c seq-FMA chain (Eigen gebp order).
        {
            const int wn = (wl_n < WLCAP) ? wl_n : WLCAP;
            for (int t = tid; t < wn; t += NTHR) {
                const int e = wl[t];
                const int p = e >> 9;
                const int k = e & 511;
                const float4* c4 = (const float4*)(cb + k * C_DIM);
                const float4* r4 = (const float4*)&rs_t[p][0];
                float dot = 0.f;
#pragma unroll 4
                for (int g = 0; g < 16; g++) {
                    float4 v = c4[g];
                    float4 r = r4[g];
                    dot = fmaf(r.x, v.x, dot);
                    dot = fmaf(r.y, v.y, dot);
                    dot = fmaf(r.z, v.z, dot);
                    dot = fmaf(r.w, v.w, dot);
                }
                float dist = __fsub_rn(g_csq[k], __fmul_rn(2.0f, dot));
                ull pk = ((ull)ford(dist) << 32) | (unsigned)k;
                atomicMin(&redmin[p], pk);               // min dist, then min k
            }
        }
        __syncthreads();

        // C: finalize pick, reset reducers + worklist
        if (tid < P_BLK) {
            idxs[q][tid] = (int)(unsigned)(redmin[tid] & 0xffffffffull);
            red1[tid]   = 0u;
            redmin[tid] = ~0ull;
        }
        if (tid == 0) wl_n = 0;
        __syncthreads();

        // D: exact elementwise update (reference rounding chain); codeword
        //    row slice fetched as ONE LDG.128; both residual layouts updated.
        {
            const int k = idxs[q][p_e];
            const float4 cw = *((const float4*)(cb + (size_t)k * C_DIM + cg_e * 4));
            const float cvv[4] = {cw.x, cw.y, cw.z, cw.w};
            float nr[4];
            double ls = 0.0;
#pragma unroll
            for (int ii = 0; ii < 4; ii++) {
                const int c = cg_e * 4 + ii;
                const float cv = cvv[ii];
                const float r  = rs[c][p_e];
                const float d  = __fsub_rn(cv, r);          // quant - residual
                const float qst = __fadd_rn(r, d);          // straight-through
                qsum[ii] = __fadd_rn(qsum[ii], qst);        // quant_out += qst
                nr[ii] = __fsub_rn(r, cv);                  // residual -= quant
                rs[c][p_e] = nr[ii];
                ls += (double)__fmul_rn(d, d);
            }
            *((float4*)&rs_t[p_e][cg_e * 4]) =
                make_float4(nr[0], nr[1], nr[2], nr[3]);
            // warp-reduce the double, single smem atomic per warp
#pragma unroll
            for (int o = 16; o; o >>= 1)
                ls += __shfl_xor_sync(0xffffffffu, ls, o);
            if (lane == 0) atomicAdd(&sloss[q], ls);
        }

        // E: fast-score cascade: acc += (-G[idx]) slices, point-pair packed
        if (q < NQ - 1) {
#pragma unroll
            for (int i = 0; i < 4; i++) {
                const int pA = pg * 8 + 2 * i;
                const int rA = idxs[q][pA];
                const int rB = idxs[q][pA + 1];
                float4 gl = *((const float4*)(g_G + (size_t)rA * K_CB + kbase));
                float4 gh = *((const float4*)(g_G + (size_t)rB * K_CB + kbase));
                acc2[i][0] = add2(acc2[i][0], pack2(gl.x, gh.x));
                acc2[i][1] = add2(acc2[i][1], pack2(gl.y, gh.y));
                acc2[i][2] = add2(acc2[i][2], pack2(gl.z, gh.z));
                acc2[i][3] = add2(acc2[i][3], pack2(gl.w, gh.w));
            }
        }
        __syncthreads();
    }

    // ---- outputs ----
    // indices as float, coalesced: 64 threads cover 16 points x 4 stages
    if (tid < P_BLK * NQ) {
        const int q = tid & 3, p = tid >> 2;
        out[IDX_OFF + (size_t)(n0 + p) * NQ + q] = (float)idxs[q][p];
    }
    // quantized in [B,C,H,W] layout (coalesced over p)
    {
        float* obase = out + (size_t)b * C_DIM * HW_SZ + hw0 + p_e;
#pragma unroll
        for (int ii = 0; ii < 4; ii++) {
            const int c = cg_e * 4 + ii;
            obase[(size_t)c * HW_SZ] = qsum[ii];
        }
    }
    // commit losses: 4 global atomics per block, last block writes output
    if (tid < NQ) atomicAdd(&g_loss[tid], sloss[tid]);
    __syncthreads();
    if (tid == 0) {
        __threadfence();
        unsigned t = atomicAdd(&g_done, 1u);
        if (t == (unsigned)(gridDim.x - 1)) {
            __threadfence();
            g_done = 0;                        // reset for next launch/replay
#pragma unroll
            for (int qq = 0; qq < NQ; qq++)
                out[LOSS_OFF + qq] =
                    (float)(g_loss[qq] * (1.0 / (131072.0 * 64.0)));
        }
    }
}

extern "C" void kernel_launch(void* const* d_in, const int* in_sizes, int n_in,
                              void* d_out, int out_size) {
    (void)in_sizes; (void)n_in; (void)out_size;
    const float* x  = (const float*)d_in[0];
    const float* cb = (const float*)d_in[1];
    float* out = (float*)d_out;

    prep_kernel<<<K_CB, 512>>>(cb);
    rvq_kernel<<<NBLK, NTHR>>>(x, cb, out);
}

// round 15
// speedup vs baseline: 1.4210x; 1.0069x over previous
#include <cuda_runtime.h>
#include <cstdint>

#define N_PTS   131072
#define C_DIM   64
#define K_CB    512
#define NQ      4
#define HW_SZ   16384
#define P_BLK   16
#define NTHR    256
#define NBLK    (N_PTS / P_BLK)
#define WLCAP   512
#define IDX_OFF 8388608
#define LOSS_OFF 8912896

typedef unsigned long long ull;

// Scratch (allocation-free rule: __device__ globals)
__device__ float    g_G[K_CB * K_CB];    // NEGATED Gram -cb@cb.T (fast path)
__device__ float    g_h[K_CB];           // NEGATED half-norms -0.5||c||^2
__device__ float    g_csq[K_CB];         // ||c||^2, XLA-CPU vectorized-reduce order
__device__ float    g_cbT[C_DIM * K_CB]; // transposed codebook [c][k]
__device__ double   g_loss[NQ];
__device__ unsigned g_done = 0;

// Packed fp32x2 ops (sm_10x). Per-lane rn rounding == scalar fmaf/fadd.
__device__ __forceinline__ ull fma2(ull a, ull b, ull c) {
    ull d;
    asm("fma.rn.f32x2 %0, %1, %2, %3;" : "=l"(d) : "l"(a), "l"(b), "l"(c));
    return d;
}
__device__ __forceinline__ ull add2(ull a, ull b) {
    ull d;
    asm("add.rn.f32x2 %0, %1, %2;" : "=l"(d) : "l"(a), "l"(b));
    return d;
}
__device__ __forceinline__ ull pack2(float lo, float hi) {
    ull d;
    asm("mov.b64 %0, {%1, %2};" : "=l"(d) : "f"(lo), "f"(hi));
    return d;
}
__device__ __forceinline__ void unpack2(float& lo, float& hi, ull v) {
    asm("mov.b64 {%0, %1}, %2;" : "=f"(lo), "=f"(hi) : "l"(v));
}

// ---------------------------------------------------------------------------
// Precompute (negated) G, (negated) h, csq, cbT; zero loss accumulators.
// ---------------------------------------------------------------------------
__global__ void prep_kernel(const float* __restrict__ cb) {
    __shared__ float ci[C_DIM];
    const int i = blockIdx.x;
    const int t = threadIdx.x;
    if (t < C_DIM) ci[t] = cb[i * C_DIM + t];
    __syncthreads();
    {
        const float4* row = (const float4*)(cb + t * C_DIM);
        float s = 0.f;
#pragma unroll
        for (int c4 = 0; c4 < 16; c4++) {
            float4 v = row[c4];
            s = fmaf(ci[4 * c4 + 0], v.x, s);
            s = fmaf(ci[4 * c4 + 1], v.y, s);
            s = fmaf(ci[4 * c4 + 2], v.z, s);
            s = fmaf(ci[4 * c4 + 3], v.w, s);
        }
        g_G[i * K_CB + t] = -s;                 // negated for packed-add subtract
        if (t == i) g_h[i] = -0.5f * s;         // negated half-norm
    }
    if (t < C_DIM) g_cbT[t * K_CB + i] = ci[t]; // transposed copy
    if (t == 0) {
        // csq exactly as XLA:CPU vectorized reduce (NEON width 4):
        // 4 strided lane accumulators, strict per-op rounding (mul+add,
        // no FMA), shuffle-halving horizontal sum: (L0+L2)+(L1+L3).
        float l0 = 0.f, l1 = 0.f, l2 = 0.f, l3 = 0.f;
        for (int j = 0; j < 16; j++) {
            float v0 = ci[4 * j + 0], v1 = ci[4 * j + 1];
            float v2 = ci[4 * j + 2], v3 = ci[4 * j + 3];
            l0 = __fadd_rn(l0, __fmul_rn(v0, v0));
            l1 = __fadd_rn(l1, __fmul_rn(v1, v1));
            l2 = __fadd_rn(l2, __fmul_rn(v2, v2));
            l3 = __fadd_rn(l3, __fmul_rn(v3, v3));
        }
        g_csq[i] = __fadd_rn(__fadd_rn(l0, l2), __fadd_rn(l1, l3));
    }
    if (i == 0 && t < NQ) g_loss[t] = 0.0;
}

// Orderable-float packing: larger float -> larger uint (monotone).
__device__ __forceinline__ unsigned ford(float f) {
    unsigned u = __float_as_uint(f);
    return (u & 0x80000000u) ? ~u : (u | 0x80000000u);
}
__device__ __forceinline__ float funord(unsigned s) {
    unsigned u = (s & 0x80000000u) ? (s ^ 0x80000000u) : ~s;
    return __uint_as_float(u);
}

// ---------------------------------------------------------------------------
// Main fused RVQ kernel. R14 tile + global window, restructured to 3 syncs
// per stage (double-buffered red1/redmin; next-stage max fused into P3;
// buffer resets in P1) and depth-2 cv prefetch in the matmul.
// ---------------------------------------------------------------------------
__global__ __launch_bounds__(NTHR, 4)
void rvq_kernel(const float* __restrict__ x, const float* __restrict__ cb,
                float* __restrict__ out) {
    __shared__ __align__(16) float rs[C_DIM][P_BLK];   // residual [c][p] (4KB)
    __shared__ __align__(16) float rs_t[P_BLK][68];    // residual [p][c] (4.25KB)
    __shared__ unsigned red1[2][P_BLK];         // fast max per point, dbl-buf
    __shared__ ull redmin[2][P_BLK];            // packed (dist,k), dbl-buf
    __shared__ int    idxs[NQ][P_BLK];
    __shared__ double sloss[NQ];
    __shared__ int    wl[WLCAP];                // candidate worklist (p<<9|k)
    __shared__ int    wl_n;

    const int tid   = threadIdx.x;
    const int lane  = tid & 31;
    const int pg    = tid & 1;                  // 0..1, 8 points each
    const int kg    = tid >> 1;                 // 0..127
    const int kbase = kg * 4;
    const int n0    = blockIdx.x * P_BLK;
    const int b     = n0 / HW_SZ;               // 16 | HW, block never crosses b
    const int hw0   = n0 % HW_SZ;
    const float* xbase = x + (size_t)b * C_DIM * HW_SZ + hw0;

    if (tid < P_BLK) {
        red1[0][tid] = 0u;    red1[1][tid] = 0u;
        redmin[0][tid] = ~0ull; redmin[1][tid] = ~0ull;
    }
    if (tid < NQ) sloss[tid] = 0.0;
    if (tid == 0) wl_n = 0;

    const int p_e  = tid & 15;       // elementwise-phase point
    const int cg_e = tid >> 4;       // elementwise-phase channel group (0..15)

    // ---- load x tile; fill BOTH residual layouts ----
    {
        float v0 = xbase[(size_t)(cg_e * 4 + 0) * HW_SZ + p_e];
        float v1 = xbase[(size_t)(cg_e * 4 + 1) * HW_SZ + p_e];
        float v2 = xbase[(size_t)(cg_e * 4 + 2) * HW_SZ + p_e];
        float v3 = xbase[(size_t)(cg_e * 4 + 3) * HW_SZ + p_e];
        rs[cg_e * 4 + 0][p_e] = v0;
        rs[cg_e * 4 + 1][p_e] = v1;
        rs[cg_e * 4 + 2][p_e] = v2;
        rs[cg_e * 4 + 3][p_e] = v3;
        *((float4*)&rs_t[p_e][cg_e * 4]) = make_float4(v0, v1, v2, v3);
    }

    // ---- acc init: packed (-0.5||c_k||^2), same value both point-halves ----
    ull acc2[4][4];
    {
        float4 hv = *((const float4*)(g_h + kbase));
        ull h0 = pack2(hv.x, hv.x), h1 = pack2(hv.y, hv.y);
        ull h2 = pack2(hv.z, hv.z), h3 = pack2(hv.w, hv.w);
#pragma unroll
        for (int i = 0; i < 4; i++) {
            acc2[i][0] = h0; acc2[i][1] = h1;
            acc2[i][2] = h2; acc2[i][3] = h3;
        }
    }
    __syncthreads();

    // ---- barrier-free matmul, depth-2 cv prefetch ----
    // Per (p,k) cell: one fma.rn per ascending c — byte-identical chain.
#define FMA_BLOCK(CC, CV)                                                  \
    do {                                                                   \
        ulonglong2 xa = *((const ulonglong2*)&rs[(CC)][pg * 8]);           \
        ulonglong2 xb = *((const ulonglong2*)&rs[(CC)][pg * 8 + 4]);       \
        ull c0 = pack2((CV).x, (CV).x), c1 = pack2((CV).y, (CV).y);        \
        ull c2 = pack2((CV).z, (CV).z), c3 = pack2((CV).w, (CV).w);        \
        acc2[0][0] = fma2(xa.x, c0, acc2[0][0]);                           \
        acc2[0][1] = fma2(xa.x, c1, acc2[0][1]);                           \
        acc2[0][2] = fma2(xa.x, c2, acc2[0][2]);                           \
        acc2[0][3] = fma2(xa.x, c3, acc2[0][3]);                           \
        acc2[1][0] = fma2(xa.y, c0, acc2[1][0]);                           \
        acc2[1][1] = fma2(xa.y, c1, acc2[1][1]);                           \
        acc2[1][2] = fma2(xa.y, c2, acc2[1][2]);                           \
        acc2[1][3] = fma2(xa.y, c3, acc2[1][3]);                           \
        acc2[2][0] = fma2(xb.x, c0, acc2[2][0]);                           \
        acc2[2][1] = fma2(xb.x, c1, acc2[2][1]);                           \
        acc2[2][2] = fma2(xb.x, c2, acc2[2][2]);                           \
        acc2[2][3] = fma2(xb.x, c3, acc2[2][3]);                           \
        acc2[3][0] = fma2(xb.y, c0, acc2[3][0]);                           \
        acc2[3][1] = fma2(xb.y, c1, acc2[3][1]);                           \
        acc2[3][2] = fma2(xb.y, c2, acc2[3][2]);                           \
        acc2[3][3] = fma2(xb.y, c3, acc2[3][3]);                           \
    } while (0)
    {
        const float4* cvp = (const float4*)(g_cbT + kbase);
        float4 cvA = __ldg(cvp);
#pragma unroll 2
        for (int c = 0; c < C_DIM - 1; c++) {
            float4 cvN = __ldg(cvp + (size_t)(c + 1) * (K_CB / 4));
            FMA_BLOCK(c, cvA);
            cvA = cvN;
        }
        FMA_BLOCK(C_DIM - 1, cvA);
    }

    // ---- A0: warp maxes of initial scores -> red1[0] (global window) ----
#pragma unroll
    for (int i = 0; i < 4; i++) {
        float l0, h0, l1, h1, l2, h2, l3, h3;
        unpack2(l0, h0, acc2[i][0]);
        unpack2(l1, h1, acc2[i][1]);
        unpack2(l2, h2, acc2[i][2]);
        unpack2(l3, h3, acc2[i][3]);
        float blo = fmaxf(fmaxf(l0, l1), fmaxf(l2, l3));
        float bhi = fmaxf(fmaxf(h0, h1), fmaxf(h2, h3));
        blo = fmaxf(blo, __shfl_xor_sync(0xffffffffu, blo, 2));
        blo = fmaxf(blo, __shfl_xor_sync(0xffffffffu, blo, 4));
        blo = fmaxf(blo, __shfl_xor_sync(0xffffffffu, blo, 8));
        blo = fmaxf(blo, __shfl_xor_sync(0xffffffffu, blo, 16));
        bhi = fmaxf(bhi, __shfl_xor_sync(0xffffffffu, bhi, 2));
        bhi = fmaxf(bhi, __shfl_xor_sync(0xffffffffu, bhi, 4));
        bhi = fmaxf(bhi, __shfl_xor_sync(0xffffffffu, bhi, 8));
        bhi = fmaxf(bhi, __shfl_xor_sync(0xffffffffu, bhi, 16));
        if (lane < 2) {
            atomicMax(&red1[0][pg * 8 + 2 * i + 0], ford(blo));
            atomicMax(&red1[0][pg * 8 + 2 * i + 1], ford(bhi));
        }
    }
    __syncthreads();

    float qsum[4];                   // quantized accumulator (4 channels of p_e)
#pragma unroll
    for (int ii = 0; ii < 4; ii++) qsum[ii] = 0.f;

    // ---- 4 quantizer stages, 3 syncs each ----
#pragma unroll
    for (int q = 0; q < NQ; q++) {
        const int buf = q & 1;

        // P1: push windowed candidates (global window from red1[buf]);
        //     reset the OTHER buffers (unread since q-1's P3 closing sync).
        if (tid < P_BLK) {
            red1[buf ^ 1][tid] = 0u;
            redmin[buf ^ 1][tid] = ~0ull;
        }
#pragma unroll
        for (int i = 0; i < 4; i++) {
            const int pLo = pg * 8 + 2 * i, pHi = pLo + 1;
            const float thrLo = funord(red1[buf][pLo]) - 0.01f;
            const float thrHi = funord(red1[buf][pHi]) - 0.01f;
            float alo[4], ahi[4];
            unpack2(alo[0], ahi[0], acc2[i][0]);
            unpack2(alo[1], ahi[1], acc2[i][1]);
            unpack2(alo[2], ahi[2], acc2[i][2]);
            unpack2(alo[3], ahi[3], acc2[i][3]);
#pragma unroll
            for (int j = 0; j < 4; j++) {
                if (alo[j] >= thrLo) {
                    int pos = atomicAdd(&wl_n, 1);
                    if (pos < WLCAP) wl[pos] = (pLo << 9) | (kbase + j);
                }
                if (ahi[j] >= thrHi) {
                    int pos = atomicAdd(&wl_n, 1);
                    if (pos < WLCAP) wl[pos] = (pHi << 9) | (kbase + j);
                }
            }
        }
        __syncthreads();

        // P2: exact (reference-order) dist per candidate, one thread each.
        {
            const int wn = (wl_n < WLCAP) ? wl_n : WLCAP;
            for (int t = tid; t < wn; t += NTHR) {
                const int e = wl[t];
                const int p = e >> 9;
                const int k = e & 511;
                const float4* c4 = (const float4*)(cb + k * C_DIM);
                const float4* r4 = (const float4*)&rs_t[p][0];
                float dot = 0.f;
#pragma unroll 4
                for (int g = 0; g < 16; g++) {           // ascending-c seq FMA
                    float4 v = c4[g];                     // (Eigen gebp order)
                    float4 r = r4[g];
                    dot = fmaf(r.x, v.x, dot);
                    dot = fmaf(r.y, v.y, dot);
                    dot = fmaf(r.z, v.z, dot);
                    dot = fmaf(r.w, v.w, dot);
                }
                float dist = __fsub_rn(g_csq[k], __fmul_rn(2.0f, dot));
                ull pk = ((ull)ford(dist) << 32) | (unsigned)k;
                atomicMin(&redmin[buf][p], pk);          // min dist, then min k
            }
        }
        __syncthreads();

        // P3: exact elementwise update + cascade + next-stage maxes + resets.
        //     (redmin[buf] is only READ here; its reset happens in q+2's P1.)
        {
            const int k = (int)(unsigned)(redmin[buf][p_e] & 0xffffffffull);
            const float4 cw = *((const float4*)(cb + (size_t)k * C_DIM + cg_e * 4));
            const float cvv[4] = {cw.x, cw.y, cw.z, cw.w};
            float nr[4];
            double ls = 0.0;
#pragma unroll
            for (int ii = 0; ii < 4; ii++) {
                const int c = cg_e * 4 + ii;
                const float cv = cvv[ii];
                const float r  = rs[c][p_e];
                const float d  = __fsub_rn(cv, r);          // quant - residual
                const float qst = __fadd_rn(r, d);          // straight-through
                qsum[ii] = __fadd_rn(qsum[ii], qst);        // quant_out += qst
                nr[ii] = __fsub_rn(r, cv);                  // residual -= quant
                rs[c][p_e] = nr[ii];
                ls += (double)__fmul_rn(d, d);
            }
            *((float4*)&rs_t[p_e][cg_e * 4]) =
                make_float4(nr[0], nr[1], nr[2], nr[3]);
#pragma unroll
            for (int o = 16; o; o >>= 1)
                ls += __shfl_xor_sync(0xffffffffu, ls, o);
            if (lane == 0) atomicAdd(&sloss[q], ls);
        }
        if (tid < P_BLK)
            idxs[q][tid] = (int)(unsigned)(redmin[buf][tid] & 0xffffffffull);

        if (q < NQ - 1) {
            // cascade: acc += (-G[idx]) slices; then next stage's warp maxes
#pragma unroll
            for (int i = 0; i < 4; i++) {
                const int pA = pg * 8 + 2 * i;
                const int rA = (int)(unsigned)(redmin[buf][pA] & 0xffffffffull);
                const int rB = (int)(unsigned)(redmin[buf][pA + 1] & 0xffffffffull);
                float4 gl = *((const float4*)(g_G + (size_t)rA * K_CB + kbase));
                float4 gh = *((const float4*)(g_G + (size_t)rB * K_CB + kbase));
                acc2[i][0] = add2(acc2[i][0], pack2(gl.x, gh.x));
                acc2[i][1] = add2(acc2[i][1], pack2(gl.y, gh.y));
                acc2[i][2] = add2(acc2[i][2], pack2(gl.z, gh.z));
                acc2[i][3] = add2(acc2[i][3], pack2(gl.w, gh.w));
                // next-stage max for this point pair
                float l0, h0, l1, h1, l2, h2, l3, h3;
                unpack2(l0, h0, acc2[i][0]);
                unpack2(l1, h1, acc2[i][1]);
                unpack2(l2, h2, acc2[i][2]);
                unpack2(l3, h3, acc2[i][3]);
                float blo = fmaxf(fmaxf(l0, l1), fmaxf(l2, l3));
                float bhi = fmaxf(fmaxf(h0, h1), fmaxf(h2, h3));
                blo = fmaxf(blo, __shfl_xor_sync(0xffffffffu, blo, 2));
                blo = fmaxf(blo, __shfl_xor_sync(0xffffffffu, blo, 4));
                blo = fmaxf(blo, __shfl_xor_sync(0xffffffffu, blo, 8));
                blo = fmaxf(blo, __shfl_xor_sync(0xffffffffu, blo, 16));
                bhi = fmaxf(bhi, __shfl_xor_sync(0xffffffffu, bhi, 2));
                bhi = fmaxf(bhi, __shfl_xor_sync(0xffffffffu, bhi, 4));
                bhi = fmaxf(bhi, __shfl_xor_sync(0xffffffffu, bhi, 16));
                bhi = fmaxf(bhi, __shfl_xor_sync(0xffffffffu, bhi, 8));
                if (lane < 2) {
                    atomicMax(&red1[buf ^ 1][pA], ford(blo));
                    atomicMax(&red1[buf ^ 1][pA + 1], ford(bhi));
                }
            }
        }
        if (tid == 0) wl_n = 0;
        __syncthreads();
    }

    // ---- outputs ----
    // indices as float, coalesced: 64 threads cover 16 points x 4 stages
    if (tid < P_BLK * NQ) {
        const int q = tid & 3, p = tid >> 2;
        out[IDX_OFF + (size_t)(n0 + p) * NQ + q] = (float)idxs[q][p];
    }
    // quantized in [B,C,H,W] layout (coalesced over p)
    {
        float* obase = out + (size_t)b * C_DIM * HW_SZ + hw0 + p_e;
#pragma unroll
        for (int ii = 0; ii < 4; ii++) {
            const int c = cg_e * 4 + ii;
            obase[(size_t)c * HW_SZ] = qsum[ii];
        }
    }
    // commit losses: 4 global atomics per block, last block writes output
    if (tid < NQ) atomicAdd(&g_loss[tid], sloss[tid]);
    __syncthreads();
    if (tid == 0) {
        __threadfence();
        unsigned t = atomicAdd(&g_done, 1u);
        if (t == (unsigned)(gridDim.x - 1)) {
            __threadfence();
            g_done = 0;                        // reset for next launch/replay
#pragma unroll
            for (int qq = 0; qq < NQ; qq++)
                out[LOSS_OFF + qq] =
                    (float)(g_loss[qq] * (1.0 / (131072.0 * 64.0)));
        }
    }
}

extern "C" void kernel_launch(void* const* d_in, const int* in_sizes, int n_in,
                              void* d_out, int out_size) {
    (void)in_sizes; (void)n_in; (void)out_size;
    const float* x  = (const float*)d_in[0];
    const float* cb = (const float*)d_in[1];
    float* out = (float*)d_out;

    prep_kernel<<<K_CB, 512>>>(cb);
    rvq_kernel<<<NBLK, NTHR>>>(x, cb, out);
}